// round 9
// baseline (speedup 1.0000x reference)
#include <cuda_runtime.h>
#include <math.h>

// Problem constants (B=1)
#define Lc     2048
#define Hc     16
#define Dc     64
#define Mc     24
#define Wc     128
#define CHUNK  128
#define NC     16
#define SCALEc 0.125f
#define EPSc   1e-4f
#define DN     0.35355339059327373f   // sqrt(0.125)
#define LN24   3.1780538303479458f    // log(24)

typedef unsigned long long U64;

__device__ __forceinline__ U64 fma2(U64 a, U64 b, U64 c) {
    U64 d; asm("fma.rn.f32x2 %0, %1, %2, %3;" : "=l"(d) : "l"(a), "l"(b), "l"(c)); return d;
}
__device__ __forceinline__ U64 mul2(U64 a, U64 b) {
    U64 d; asm("mul.rn.f32x2 %0, %1, %2;" : "=l"(d) : "l"(a), "l"(b)); return d;
}
__device__ __forceinline__ U64 add2(U64 a, U64 b) {
    U64 d; asm("add.rn.f32x2 %0, %1, %2;" : "=l"(d) : "l"(a), "l"(b)); return d;
}
__device__ __forceinline__ U64 pack2(float x, float y) {
    U64 d; asm("mov.b64 %0, {%1,%2};" : "=l"(d)
               : "r"(__float_as_uint(x)), "r"(__float_as_uint(y))); return d;
}
__device__ __forceinline__ float hadd2(U64 a) {
    unsigned lo, hi; asm("mov.b64 {%0,%1}, %2;" : "=r"(lo), "=r"(hi) : "l"(a));
    return __uint_as_float(lo) + __uint_as_float(hi);
}
__device__ __forceinline__ void unpack2(float& x, float& y, U64 a) {
    unsigned lo, hi; asm("mov.b64 {%0,%1}, %2;" : "=r"(lo), "=r"(hi) : "l"(a));
    x = __uint_as_float(lo); y = __uint_as_float(hi);
}

#define CP_COMMIT() asm volatile("cp.async.commit_group;")
#define CP_WAIT(n)  asm volatile("cp.async.wait_group %0;" :: "n"(n))

// ---------------- scratch ----------------
__device__ float  g_kprime[Hc * Lc * Mc];          // p = exp(xd - xn - locmax_c)
__device__ float  g_chunkmax[Hc * NC];             // locmax per (h,c)
__device__ float  g_psum [Hc * NC * Mc];           // per-chunk sum of p
__device__ float  g_pvsum[Hc * NC * Mc * Dc];      // per-chunk sum of p (x) v
__device__ float  g_vsum [Hc * NC * Dc];           // per-chunk sum of v
__device__ float  g_qprime[Hc * Lc * Mc];          // q' features
__device__ float2 g_qmeta[Hc * Lc];                // (qstab - xn_q, EPS*sum(q'))

__device__ __forceinline__ float sdot64(const float* krow, const U64* q2) {
    const ulonglong2* kr = (const ulonglong2*)krow;
    U64 a0, a1, a2, a3;
    {
        ulonglong2 x = kr[0]; a0 = mul2(q2[0], x.x); a1 = mul2(q2[1], x.y);
        ulonglong2 y = kr[1]; a2 = mul2(q2[2], y.x); a3 = mul2(q2[3], y.y);
    }
#pragma unroll
    for (int u = 2; u < 16; u += 2) {
        ulonglong2 x = kr[u];     a0 = fma2(q2[2*u],   x.x, a0); a1 = fma2(q2[2*u+1], x.y, a1);
        ulonglong2 y = kr[u + 1]; a2 = fma2(q2[2*u+2], y.x, a2); a3 = fma2(q2[2*u+3], y.y, a3);
    }
    return hadd2(add2(add2(a0, a1), add2(a2, a3)));
}

// ---------------- prep: role-split (z=0: K+sums, z=1: Q features) ----------
// smem (floats): proj 1536 @0 | vbuf 8192 @1536 | kp 3200 @9728 | red4 @12928
#define SM12_FLOATS 12944

__global__ void __launch_bounds__(128) k12_prep(const float* __restrict__ qkv,
                                                const float* __restrict__ proj)
{
    extern __shared__ float sm[];
    float* proj_s = sm;

    const int c = blockIdx.x, h = blockIdx.y, t = threadIdx.x;
    const int role = blockIdx.z;
    const int hc = h * NC + c;
    const int tilebase = c * CHUNK;
    const int l = tilebase + t;

    for (int f = t; f < 384; f += 128)
        ((float4*)proj_s)[f] = ((const float4*)proj)[f];

    if (role == 1) {
        // ---- query features only ----
        __syncthreads();
        U64 q2r[32];
        {
            const ulonglong2* qr = (const ulonglong2*)(qkv + ((size_t)(l * 3) * Hc + h) * Dc);
#pragma unroll
            for (int u = 0; u < 16; u++) { ulonglong2 x = qr[u]; q2r[2*u] = x.x; q2r[2*u+1] = x.y; }
        }
        float xnq;
        {
            U64 a0 = mul2(q2r[0], q2r[0]), a1 = mul2(q2r[1], q2r[1]);
            U64 a2 = mul2(q2r[2], q2r[2]), a3 = mul2(q2r[3], q2r[3]);
#pragma unroll
            for (int u = 4; u < 32; u += 4) {
                a0 = fma2(q2r[u],   q2r[u],   a0);
                a1 = fma2(q2r[u+1], q2r[u+1], a1);
                a2 = fma2(q2r[u+2], q2r[u+2], a2);
                a3 = fma2(q2r[u+3], q2r[u+3], a3);
            }
            xnq = hadd2(add2(add2(a0, a1), add2(a2, a3))) * 0.0625f;
        }
        float xdq[Mc];
        float qstab = -3.4e38f;
#pragma unroll
        for (int m = 0; m < Mc; m++) {
            xdq[m] = sdot64(proj_s + m * Dc, q2r) * DN;
            qstab = fmaxf(qstab, xdq[m]);
        }
        float qp[Mc];
        float qpsum = 0.f;
#pragma unroll
        for (int m = 0; m < Mc; m++) {
            qp[m] = __expf(xdq[m] - qstab) + EPSc;
            qpsum += qp[m];
        }
        float4* qpo = (float4*)(g_qprime + ((size_t)h * Lc + l) * Mc);
#pragma unroll
        for (int e = 0; e < 6; e++)
            qpo[e] = make_float4(qp[4*e], qp[4*e+1], qp[4*e+2], qp[4*e+3]);
        g_qmeta[(size_t)h * Lc + l] = make_float2(qstab - xnq, EPSc * qpsum);
        return;
    }

    // ---- role 0: key features + chunk sums ----
    float* vbuf = sm + 1536;
    float* kp_s = sm + 9728;    // stride 25
    float* red4 = sm + 12928;

    for (int f = t; f < 2048; f += 128) {
        int r = f >> 4, dv = f & 15;
        ((float4*)vbuf)[f] =
            ((const float4*)(qkv + ((size_t)((tilebase + r) * 3 + 2) * Hc + h) * Dc))[dv];
    }
    __syncthreads();

    U64 k2r[32];
    {
        const ulonglong2* kr = (const ulonglong2*)(qkv + ((size_t)(l * 3 + 1) * Hc + h) * Dc);
#pragma unroll
        for (int u = 0; u < 16; u++) { ulonglong2 x = kr[u]; k2r[2*u] = x.x; k2r[2*u+1] = x.y; }
    }
    float xn;
    {
        U64 a0 = mul2(k2r[0], k2r[0]), a1 = mul2(k2r[1], k2r[1]);
        U64 a2 = mul2(k2r[2], k2r[2]), a3 = mul2(k2r[3], k2r[3]);
#pragma unroll
        for (int u = 4; u < 32; u += 4) {
            a0 = fma2(k2r[u],   k2r[u],   a0);
            a1 = fma2(k2r[u+1], k2r[u+1], a1);
            a2 = fma2(k2r[u+2], k2r[u+2], a2);
            a3 = fma2(k2r[u+3], k2r[u+3], a3);
        }
        xn = hadd2(add2(add2(a0, a1), add2(a2, a3))) * 0.0625f;
    }
    float xd[Mc];
    float mx = -3.4e38f;
#pragma unroll
    for (int m = 0; m < Mc; m++) {
        xd[m] = sdot64(proj_s + m * Dc, k2r) * DN;
        mx = fmaxf(mx, xd[m]);
    }
#pragma unroll
    for (int off = 16; off > 0; off >>= 1)
        mx = fmaxf(mx, __shfl_xor_sync(0xffffffffu, mx, off));
    if ((t & 31) == 0) red4[t >> 5] = mx;
    __syncthreads();

    const float locmax = fmaxf(fmaxf(red4[0], red4[1]), fmaxf(red4[2], red4[3]));
    if (t == 0) g_chunkmax[hc] = locmax;

    float p[Mc];
#pragma unroll
    for (int m = 0; m < Mc; m++) {
        p[m] = __expf(xd[m] - xn - locmax);
        kp_s[t * 25 + m] = p[m];
    }
    {
        float4* kpo = (float4*)(g_kprime + ((size_t)h * Lc + l) * Mc);
#pragma unroll
        for (int e = 0; e < 6; e++)
            kpo[e] = make_float4(p[4*e], p[4*e+1], p[4*e+2], p[4*e+3]);
    }
    __syncthreads();

    float4* pvo4 = (float4*)(g_pvsum + (size_t)hc * Mc * Dc);
    const float4* vb4 = (const float4*)vbuf;
#pragma unroll
    for (int grp = 0; grp < 3; grp++) {
        int o = t + 128 * grp;
        int m = o >> 4, d4 = o & 15;
        float4 a = make_float4(0.f, 0.f, 0.f, 0.f);
        for (int row = 0; row < CHUNK; row++) {
            float kp = kp_s[row * 25 + m];
            float4 v = vb4[row * 16 + d4];
            a.x = fmaf(kp, v.x, a.x);
            a.y = fmaf(kp, v.y, a.y);
            a.z = fmaf(kp, v.z, a.z);
            a.w = fmaf(kp, v.w, a.w);
        }
        pvo4[o] = a;
    }
    if (t < Mc) {
        float a = 0.f;
        for (int row = 0; row < CHUNK; row++) a += kp_s[row * 25 + t];
        g_psum[hc * Mc + t] = a;
    }
    if (t >= 32 && t < 48) {
        int t16 = t - 32;
        float4 a = make_float4(0.f, 0.f, 0.f, 0.f);
        for (int row = 0; row < CHUNK; row++) {
            float4 v = vb4[row * 16 + t16];
            a.x += v.x; a.y += v.y; a.z += v.z; a.w += v.w;
        }
        ((float4*)(g_vsum + (size_t)hc * Dc))[t16] = a;
    }
}

// ---------------- kernel 4: single-pass fused attention ----------
// smem (floats): K 16384 @0 | kp 6144 @16384 | kvb 1536 @22528
//   | kb 32 @24064 | sv 64 @24096 | ring 4096 @24160 | total 28256 = 110.4 KB
#define OFF_K    0
#define OFF_KP   16384
#define OFF_KVB  22528
#define OFF_KB   24064
#define OFF_SV   24096
#define OFF_RING 24160
#define SM4_FLOATS 28256

__device__ __forceinline__ float gdot24(const float* kprow, const U64* qp2) {
    const ulonglong2* pr = (const ulonglong2*)kprow;
    ulonglong2 y0 = pr[0], y1 = pr[1], y2 = pr[2];
    U64 g0 = mul2(qp2[0], y0.x), g1 = mul2(qp2[1], y0.y);
    g0 = fma2(qp2[2], y1.x, g0);  g1 = fma2(qp2[3], y1.y, g1);
    g0 = fma2(qp2[4], y2.x, g0);  g1 = fma2(qp2[5], y2.y, g1);
    ulonglong2 y3 = pr[3], y4 = pr[4], y5 = pr[5];
    g0 = fma2(qp2[6],  y3.x, g0); g1 = fma2(qp2[7],  y3.y, g1);
    g0 = fma2(qp2[8],  y4.x, g0); g1 = fma2(qp2[9],  y4.y, g1);
    g0 = fma2(qp2[10], y5.x, g0); g1 = fma2(qp2[11], y5.y, g1);
    return hadd2(add2(g0, g1));
}

// dual accumulate: P += es*v, G += gw*v
__device__ __forceinline__ void vacc2(U64 es2, U64 gw2, const float* vrow,
                                      U64* P2, U64* G2) {
    const ulonglong2* vr = (const ulonglong2*)vrow;
#pragma unroll
    for (int u = 0; u < 16; u++) {
        ulonglong2 x = vr[u];
        P2[2*u]   = fma2(es2, x.x, P2[2*u]);
        P2[2*u+1] = fma2(es2, x.y, P2[2*u+1]);
        G2[2*u]   = fma2(gw2, x.x, G2[2*u]);
        G2[2*u+1] = fma2(gw2, x.y, G2[2*u+1]);
    }
}

__device__ __forceinline__ void stage2v(const float* __restrict__ qkv, int h,
                                        unsigned ringw_u32, int slot,
                                        int ra, int rb, int lane)
{
    int row = (lane < 16) ? ra : rb;
    const float* src = qkv + ((size_t)(row * 3 + 2) * Hc + h) * Dc + (lane & 15) * 4;
    unsigned dst = ringw_u32 + (unsigned)(slot * 512 + ((lane >> 4) * 256) + (lane & 15) * 16);
    asm volatile("cp.async.cg.shared.global [%0], [%1], 16;" :: "r"(dst), "l"(src));
}

__global__ void __launch_bounds__(128, 2) k4_main(const float* __restrict__ qkv,
                                                  float* __restrict__ out)
{
    extern __shared__ float sm[];
    float* K_s    = sm + OFF_K;
    float* kp_s   = sm + OFF_KP;
    float* kvb_s  = sm + OFF_KVB;
    float* kb_s   = sm + OFF_KB;
    float* sv_s   = sm + OFF_SV;
    float* ring   = sm + OFF_RING;

    const int c = blockIdx.x, h = blockIdx.y, t = threadIdx.x;
    const int warp = t >> 5, lane = t & 31;
    const int cstart = c * CHUNK;
    const int i = cstart + t;
    const int tilebase = (c > 0) ? (c - 1) * CHUNK : 0;
    const int nkeys    = (c > 0) ? 256 : 128;
    const int cb = (c > 0) ? 128 : 0;

    // ---- stabilizer + alpha factors ----
    float alf[NC];
    float kstab;
    {
        float cm[NC];
        kstab = -3.4e38f;
#pragma unroll
        for (int cc = 0; cc < NC; cc++) {
            cm[cc] = __ldg(&g_chunkmax[h * NC + cc]);
            kstab = fmaxf(kstab, cm[cc]);
        }
#pragma unroll
        for (int cc = 0; cc < NC; cc++) alf[cc] = __expf(cm[cc] - kstab);
    }
    const float alphaP = (c > 0) ? alf[c - 1] : 0.f;
    const float alphaC = alf[c];

    // ---- cooperative tile load ----
    for (int f = t; f < nkeys * 16; f += 128) {
        int r = f >> 4, dv = f & 15;
        ((float4*)K_s)[r * 16 + dv] =
            ((const float4*)(qkv + ((size_t)((tilebase + r) * 3 + 1) * Hc + h) * Dc))[dv];
    }
    {
        const float4* kpsrc = (const float4*)(g_kprime + ((size_t)h * Lc + tilebase) * Mc);
        for (int f = t; f < nkeys * 6; f += 128) ((float4*)kp_s)[f] = kpsrc[f];
    }
    // ---- prefix reconstruction: kvb (alpha-weighted), kb, sv ----
#pragma unroll
    for (int g = 0; g < 3; g++) {
        int f = t + 128 * g;
        float4 a = make_float4(0.f, 0.f, 0.f, 0.f);
        for (int cc = 0; cc < c; cc++) {
            float al = alf[cc];
            float4 x = __ldg((const float4*)g_pvsum + (size_t)(h * NC + cc) * 384 + f);
            a.x = fmaf(al, x.x, a.x); a.y = fmaf(al, x.y, a.y);
            a.z = fmaf(al, x.z, a.z); a.w = fmaf(al, x.w, a.w);
        }
        ((float4*)kvb_s)[f] = a;
    }
    if (t < Mc) {
        float a = (float)c * (CHUNK * EPSc);
        for (int cc = 0; cc < c; cc++)
            a = fmaf(alf[cc], __ldg(&g_psum[(h * NC + cc) * Mc + t]), a);
        kb_s[t] = a;
    }
    if (t < 16) {
        float4 a = make_float4(0.f, 0.f, 0.f, 0.f);
        for (int cc = 0; cc < c; cc++) {
            float4 x = __ldg((const float4*)(g_vsum + (size_t)(h * NC + cc) * Dc) + t);
            a.x += x.x; a.y += x.y; a.z += x.z; a.w += x.w;
        }
        ((float4*)sv_s)[t] = a;
    }
    __syncthreads();

    // ---- query state: q row + precomputed q' ----
    U64 q2[32];
    {
        const ulonglong2* qr = (const ulonglong2*)(qkv + ((size_t)(i * 3) * Hc + h) * Dc);
#pragma unroll
        for (int u = 0; u < 16; u++) { ulonglong2 x = qr[u]; q2[2*u] = x.x; q2[2*u+1] = x.y; }
    }
    U64 qp2[12];
    {
        const ulonglong2* qpr = (const ulonglong2*)(g_qprime + ((size_t)h * Lc + i) * Mc);
#pragma unroll
        for (int u = 0; u < 6; u++) {
            ulonglong2 x = __ldg(&qpr[u]);
            qp2[2*u] = x.x; qp2[2*u+1] = x.y;
        }
    }
    const float2 qm = __ldg(&g_qmeta[(size_t)h * Lc + i]);
    const float epsqp = qm.y;
    const float gs = qm.x + kstab - LN24;

    float kbdot = 0.f;
#pragma unroll
    for (int e = 0; e < 12; e++) {
        float a, b; unpack2(a, b, qp2[e]);
        kbdot = fmaf(a, kb_s[2*e],     kbdot);
        kbdot = fmaf(b, kb_s[2*e + 1], kbdot);
    }

    // ---- single fused pass: Z, Aw, P = sum(es*v), G = sum(gw*v) ----
    U64 P2[32], G2[32];
#pragma unroll
    for (int u = 0; u < 32; u++) { P2[u] = 0ULL; G2[u] = 0ULL; }
    float Z = 0.f, Aw = 0.f;

    const float aPw = -0.125f * alphaP, ePw = -0.125f * epsqp;
    const float aCw =  0.875f * alphaC, eCw =  0.875f * epsqp;

    const int j0 = 32 * warp;
    const unsigned ringw_u32 =
        (unsigned)__cvta_generic_to_shared(ring + warp * 1024);
    const float* ringw = ring + warp * 1024;

    if (c > 0) {
        const int nbat = (128 - j0) >> 1;
#pragma unroll
        for (int p = 0; p < 7; p++) {
            int ra = j0 + 2*p;     if (ra > 127) ra = 127;
            int rb = j0 + 2*p + 1; if (rb > 127) rb = 127;
            stage2v(qkv, h, ringw_u32, p & 7, tilebase + ra, tilebase + rb, lane);
            CP_COMMIT();
        }
#pragma unroll 1
        for (int b = 0; b < nbat; b++) {
            int sp = b + 7;
            int ra = j0 + 2*sp;     if (ra > 127) ra = 127;
            int rb = j0 + 2*sp + 1; if (rb > 127) rb = 127;
            stage2v(qkv, h, ringw_u32, sp & 7, tilebase + ra, tilebase + rb, lane);
            CP_COMMIT();
            CP_WAIT(7);
            __syncwarp();
            const float* vb = ringw + (b & 7) * 128;
#pragma unroll
            for (int e = 0; e < 2; e++) {
                const int jr = j0 + 2*b + e;
                float s  = sdot64(K_s + jr * Dc, q2) * SCALEc;
                float gp = gdot24(kp_s + jr * Mc, qp2);
                float gw = fmaf(aPw, gp, ePw);
                const bool act = (jr >= t);
                float es = act ? __expf(s) : 0.f;
                gw = act ? gw : 0.f;
                Z += es; Aw += gw;
                vacc2(pack2(es, es), pack2(gw, gw), vb + e * 64, P2, G2);
            }
        }
        CP_WAIT(0);
        __syncwarp();
    }
    {
        const int jend = j0 + 32;
        const int nbat = jend >> 1;
#pragma unroll
        for (int p = 0; p < 7; p++) {
            int ra = 2*p;     if (ra > jend - 1) ra = jend - 1;
            int rb = 2*p + 1; if (rb > jend - 1) rb = jend - 1;
            stage2v(qkv, h, ringw_u32, p & 7, cstart + ra, cstart + rb, lane);
            CP_COMMIT();
        }
#pragma unroll 1
        for (int b = 0; b < nbat; b++) {
            int sp = b + 7;
            int ra = 2*sp;     if (ra > jend - 1) ra = jend - 1;
            int rb = 2*sp + 1; if (rb > jend - 1) rb = jend - 1;
            stage2v(qkv, h, ringw_u32, sp & 7, cstart + ra, cstart + rb, lane);
            CP_COMMIT();
            CP_WAIT(7);
            __syncwarp();
            const float* vb = ringw + (b & 7) * 128;
#pragma unroll
            for (int e = 0; e < 2; e++) {
                const int jc = 2*b + e;
                float s  = sdot64(K_s + (cb + jc) * Dc, q2) * SCALEc;
                float gp = gdot24(kp_s + (cb + jc) * Mc, qp2);
                float gw = fmaf(aCw, gp, eCw);
                const bool act = (jc <= t);
                float es = act ? __expf(s) : 0.f;
                gw = act ? gw : 0.f;
                Z += es; Aw += gw;
                vacc2(pack2(es, es), pack2(gw, gw), vb + e * 64, P2, G2);
            }
        }
        CP_WAIT(0);
        __syncwarp();
    }

    // ---- normalization scalars ----
    const float lse = __logf(Z);
    const float gln = __logf(fmaxf(kbdot + Aw, 1e-24f)) + gs;
    float a_ = fmaxf(lse, gln), b_ = fminf(lse, gln);
    const float lnorm = a_ + log1pf(__expf(b_ - a_));
    const float gps  = __expf(gs - lnorm);
    const float invZ = 1.f / Z;

    // ---- combine: o = invZ*P + gps*G (in place into P2) ----
    const U64 iz2 = pack2(invZ, invZ), gp2c = pack2(gps, gps);
#pragma unroll
    for (int u = 0; u < 32; u++)
        P2[u] = fma2(gp2c, G2[u], mul2(iz2, P2[u]));

    // ---- epilogue: o += gps*(q' . KVbase_alpha) + gps*qpsum*EPS * sv ----
#pragma unroll
    for (int e = 0; e < 12; e++) {
        float qa, qb; unpack2(qa, qb, qp2[e]);
        U64 ca  = pack2(gps * qa, gps * qa);
        U64 cb2 = pack2(gps * qb, gps * qb);
        const ulonglong2* r0 = (const ulonglong2*)(kvb_s + (2*e) * Dc);
        const ulonglong2* r1 = (const ulonglong2*)(kvb_s + (2*e + 1) * Dc);
#pragma unroll
        for (int u = 0; u < 16; u++) {
            ulonglong2 x0 = r0[u];
            ulonglong2 x1 = r1[u];
            P2[2*u]   = fma2(ca,  x0.x, P2[2*u]);
            P2[2*u+1] = fma2(ca,  x0.y, P2[2*u+1]);
            P2[2*u]   = fma2(cb2, x1.x, P2[2*u]);
            P2[2*u+1] = fma2(cb2, x1.y, P2[2*u+1]);
        }
    }
    {
        float csv = gps * epsqp;
        U64 c2 = pack2(csv, csv);
        const ulonglong2* vr = (const ulonglong2*)sv_s;
#pragma unroll
        for (int u = 0; u < 16; u++) {
            ulonglong2 x = vr[u];
            P2[2*u]   = fma2(c2, x.x, P2[2*u]);
            P2[2*u+1] = fma2(c2, x.y, P2[2*u+1]);
        }
    }

    ulonglong2* orow = (ulonglong2*)(out + ((size_t)i * Hc + h) * Dc);
#pragma unroll
    for (int u = 0; u < 16; u++) {
        ulonglong2 w2; w2.x = P2[2*u]; w2.y = P2[2*u+1];
        orow[u] = w2;
    }
}

// ---------------- launch ----------------
extern "C" void kernel_launch(void* const* d_in, const int* in_sizes, int n_in,
                              void* d_out, int out_size)
{
    (void)out_size;
    const float* qkv  = (const float*)d_in[0];
    const float* proj = (const float*)d_in[1];
    if (n_in >= 2 && in_sizes[0] < in_sizes[1]) {
        const float* tmp = qkv; qkv = proj; proj = tmp;
    }
    float* out = (float*)d_out;

    cudaFuncSetAttribute(k12_prep, cudaFuncAttributeMaxDynamicSharedMemorySize,
                         SM12_FLOATS * (int)sizeof(float));
    cudaFuncSetAttribute(k4_main, cudaFuncAttributeMaxDynamicSharedMemorySize,
                         SM4_FLOATS * (int)sizeof(float));

    k12_prep<<<dim3(NC, Hc, 2), 128, SM12_FLOATS * (int)sizeof(float)>>>(qkv, proj);
    k4_main <<<dim3(NC, Hc),    128, SM4_FLOATS  * (int)sizeof(float)>>>(qkv, out);
}

// round 10
// speedup vs baseline: 1.8388x; 1.8388x over previous
#include <cuda_runtime.h>
#include <math.h>

// Problem constants (B=1)
#define Lc     2048
#define Hc     16
#define Dc     64
#define Mc     24
#define Wc     128
#define CHUNK  128
#define NC     16
#define SCALEc 0.125f
#define EPSc   1e-4f
#define DN     0.35355339059327373f   // sqrt(0.125)
#define LN24   3.1780538303479458f    // log(24)
#define SCL2E  0.18033688011112042f   // 0.125 * log2(e)

typedef unsigned long long U64;

__device__ __forceinline__ U64 fma2(U64 a, U64 b, U64 c) {
    U64 d; asm("fma.rn.f32x2 %0, %1, %2, %3;" : "=l"(d) : "l"(a), "l"(b), "l"(c)); return d;
}
__device__ __forceinline__ U64 mul2(U64 a, U64 b) {
    U64 d; asm("mul.rn.f32x2 %0, %1, %2;" : "=l"(d) : "l"(a), "l"(b)); return d;
}
__device__ __forceinline__ U64 add2(U64 a, U64 b) {
    U64 d; asm("add.rn.f32x2 %0, %1, %2;" : "=l"(d) : "l"(a), "l"(b)); return d;
}
__device__ __forceinline__ U64 pack2(float x, float y) {
    U64 d; asm("mov.b64 %0, {%1,%2};" : "=l"(d)
               : "r"(__float_as_uint(x)), "r"(__float_as_uint(y))); return d;
}
__device__ __forceinline__ float hadd2(U64 a) {
    unsigned lo, hi; asm("mov.b64 {%0,%1}, %2;" : "=r"(lo), "=r"(hi) : "l"(a));
    return __uint_as_float(lo) + __uint_as_float(hi);
}
__device__ __forceinline__ void unpack2(float& x, float& y, U64 a) {
    unsigned lo, hi; asm("mov.b64 {%0,%1}, %2;" : "=r"(lo), "=r"(hi) : "l"(a));
    x = __uint_as_float(lo); y = __uint_as_float(hi);
}

#define CP_COMMIT() asm volatile("cp.async.commit_group;")
#define CP_WAIT(n)  asm volatile("cp.async.wait_group %0;" :: "n"(n))

// ---------------- scratch ----------------
__device__ float g_kprime[Hc * Lc * Mc];          // p = exp(xd - xn - locmax_c)
__device__ float g_chunkmax[Hc * NC];             // locmax per (h,c)
__device__ float g_psum [Hc * NC * Mc];           // per-chunk sum of p
__device__ float g_pvsum[Hc * NC * Mc * Dc];      // per-chunk sum of p (x) v
__device__ float g_vsum [Hc * NC * Dc];           // per-chunk sum of v

__device__ __forceinline__ float sdot64(const float* krow, const U64* q2) {
    const ulonglong2* kr = (const ulonglong2*)krow;
    U64 a0, a1, a2, a3;
    {
        ulonglong2 x = kr[0]; a0 = mul2(q2[0], x.x); a1 = mul2(q2[1], x.y);
        ulonglong2 y = kr[1]; a2 = mul2(q2[2], y.x); a3 = mul2(q2[3], y.y);
    }
#pragma unroll
    for (int u = 2; u < 16; u += 2) {
        ulonglong2 x = kr[u];     a0 = fma2(q2[2*u],   x.x, a0); a1 = fma2(q2[2*u+1], x.y, a1);
        ulonglong2 y = kr[u + 1]; a2 = fma2(q2[2*u+2], y.x, a2); a3 = fma2(q2[2*u+3], y.y, a3);
    }
    return hadd2(add2(add2(a0, a1), add2(a2, a3)));
}

// ---------------- kernel 12: fused key features + chunk sums ----------------
// smem (floats): proj 1536 @0 | vbuf 8192 @1536 | kp 3200 @9728 | red 128 @12928
#define SM12_FLOATS 13056

__global__ void __launch_bounds__(128) k12_prep(const float* __restrict__ qkv,
                                                const float* __restrict__ proj)
{
    extern __shared__ float sm[];
    float* proj_s = sm;
    float* vbuf   = sm + 1536;
    float* kp_s   = sm + 9728;    // stride 25
    float* red    = sm + 12928;

    const int c = blockIdx.x, h = blockIdx.y, t = threadIdx.x;
    const int hc = h * NC + c;
    const int tilebase = c * CHUNK;

    for (int f = t; f < 384; f += 128)
        ((float4*)proj_s)[f] = ((const float4*)proj)[f];
    for (int f = t; f < 2048; f += 128) {
        int r = f >> 4, dv = f & 15;
        ((float4*)vbuf)[f] =
            ((const float4*)(qkv + ((size_t)((tilebase + r) * 3 + 2) * Hc + h) * Dc))[dv];
    }
    __syncthreads();

    // key row into packed regs
    U64 k2r[32];
    {
        const ulonglong2* kr = (const ulonglong2*)(qkv + ((size_t)((tilebase + t) * 3 + 1) * Hc + h) * Dc);
#pragma unroll
        for (int u = 0; u < 16; u++) { ulonglong2 x = kr[u]; k2r[2*u] = x.x; k2r[2*u+1] = x.y; }
    }
    float xn;
    {
        U64 a0 = mul2(k2r[0], k2r[0]), a1 = mul2(k2r[1], k2r[1]);
        U64 a2 = mul2(k2r[2], k2r[2]), a3 = mul2(k2r[3], k2r[3]);
#pragma unroll
        for (int u = 4; u < 32; u += 4) {
            a0 = fma2(k2r[u],   k2r[u],   a0);
            a1 = fma2(k2r[u+1], k2r[u+1], a1);
            a2 = fma2(k2r[u+2], k2r[u+2], a2);
            a3 = fma2(k2r[u+3], k2r[u+3], a3);
        }
        xn = hadd2(add2(add2(a0, a1), add2(a2, a3))) * 0.0625f;
    }
    float xd[Mc];
    float mx = -3.4e38f;
#pragma unroll
    for (int m = 0; m < Mc; m++) {
        xd[m] = sdot64(proj_s + m * Dc, k2r) * DN;
        mx = fmaxf(mx, xd[m]);
    }
    red[t] = mx;
    __syncthreads();
    for (int s = 64; s > 0; s >>= 1) {
        if (t < s) red[t] = fmaxf(red[t], red[t + s]);
        __syncthreads();
    }
    const float locmax = red[0];
    if (t == 0) g_chunkmax[hc] = locmax;

    float p[Mc];
#pragma unroll
    for (int m = 0; m < Mc; m++) {
        p[m] = __expf(xd[m] - xn - locmax);
        kp_s[t * 25 + m] = p[m];
    }
    {
        float4* kpo = (float4*)(g_kprime + ((size_t)h * Lc + tilebase + t) * Mc);
#pragma unroll
        for (int e = 0; e < 6; e++)
            kpo[e] = make_float4(p[4*e], p[4*e+1], p[4*e+2], p[4*e+3]);
    }
    __syncthreads();

    // pvsum (24x64), psum (24), vsum (64)
    float4* pvo4 = (float4*)(g_pvsum + (size_t)hc * Mc * Dc);
    const float4* vb4 = (const float4*)vbuf;
#pragma unroll
    for (int grp = 0; grp < 3; grp++) {
        int o = t + 128 * grp;
        int m = o >> 4, d4 = o & 15;
        float4 a = make_float4(0.f, 0.f, 0.f, 0.f);
        for (int row = 0; row < CHUNK; row++) {
            float kp = kp_s[row * 25 + m];
            float4 v = vb4[row * 16 + d4];
            a.x = fmaf(kp, v.x, a.x);
            a.y = fmaf(kp, v.y, a.y);
            a.z = fmaf(kp, v.z, a.z);
            a.w = fmaf(kp, v.w, a.w);
        }
        pvo4[o] = a;
    }
    if (t < Mc) {
        float a = 0.f;
        for (int row = 0; row < CHUNK; row++) a += kp_s[row * 25 + t];
        g_psum[hc * Mc + t] = a;
    }
    if (t >= 32 && t < 48) {
        int t16 = t - 32;
        float4 a = make_float4(0.f, 0.f, 0.f, 0.f);
        for (int row = 0; row < CHUNK; row++) {
            float4 v = vb4[row * 16 + t16];
            a.x += v.x; a.y += v.y; a.z += v.z; a.w += v.w;
        }
        ((float4*)(g_vsum + (size_t)hc * Dc))[t16] = a;
    }
}

// ---------------- kernel 4: fused attention ----------
// smem (floats): K 16384 @0 | kp 6144 @16384 | kvb 1536 @22528
//   | proj 1536 @24064 | kb 32 @25600 | sv 64 @25632 | ring 2048 @25696
#define OFF_K    0
#define OFF_KP   16384
#define OFF_KVB  22528
#define OFF_PROJ 24064
#define OFF_KB   25600
#define OFF_SV   25632
#define OFF_RING 25696
#define SM4_FLOATS 27744

__device__ __forceinline__ float gdot24(const float* kprow, const U64* qp2) {
    const ulonglong2* pr = (const ulonglong2*)kprow;
    ulonglong2 y0 = pr[0], y1 = pr[1], y2 = pr[2];
    U64 g0 = mul2(qp2[0], y0.x), g1 = mul2(qp2[1], y0.y);
    g0 = fma2(qp2[2], y1.x, g0);  g1 = fma2(qp2[3], y1.y, g1);
    g0 = fma2(qp2[4], y2.x, g0);  g1 = fma2(qp2[5], y2.y, g1);
    ulonglong2 y3 = pr[3], y4 = pr[4], y5 = pr[5];
    g0 = fma2(qp2[6],  y3.x, g0); g1 = fma2(qp2[7],  y3.y, g1);
    g0 = fma2(qp2[8],  y4.x, g0); g1 = fma2(qp2[9],  y4.y, g1);
    g0 = fma2(qp2[10], y5.x, g0); g1 = fma2(qp2[11], y5.y, g1);
    return hadd2(add2(g0, g1));
}

__device__ __forceinline__ void vacc64(U64 c2, const float* vrow, U64* o2) {
    const ulonglong2* vr = (const ulonglong2*)vrow;
#pragma unroll
    for (int u = 0; u < 16; u++) {
        ulonglong2 x = vr[u];
        o2[2*u]   = fma2(c2, x.x, o2[2*u]);
        o2[2*u+1] = fma2(c2, x.y, o2[2*u+1]);
    }
}

// stage 2 V rows (global key indices ra, rb) into ring slot; one LDGSTS inst
__device__ __forceinline__ void stage2v(const float* __restrict__ qkv, int h,
                                        unsigned ringw_u32, int slot,
                                        int ra, int rb, int lane)
{
    int row = (lane < 16) ? ra : rb;
    const float* src = qkv + ((size_t)(row * 3 + 2) * Hc + h) * Dc + (lane & 15) * 4;
    unsigned dst = ringw_u32 + (unsigned)(slot * 512 + ((lane >> 4) * 256) + (lane & 15) * 16);
    asm volatile("cp.async.cg.shared.global [%0], [%1], 16;" :: "r"(dst), "l"(src));
}

__global__ void __launch_bounds__(128, 2) k4_main(const float* __restrict__ qkv,
                                                  const float* __restrict__ proj,
                                                  float* __restrict__ out)
{
    extern __shared__ float sm[];
    float* K_s    = sm + OFF_K;
    float* kp_s   = sm + OFF_KP;
    float* kvb_s  = sm + OFF_KVB;
    float* proj_s = sm + OFF_PROJ;
    float* kb_s   = sm + OFF_KB;
    float* sv_s   = sm + OFF_SV;
    float* ring   = sm + OFF_RING;

    const int c = blockIdx.x, h = blockIdx.y, t = threadIdx.x;
    const int warp = t >> 5, lane = t & 31;
    const int cstart = c * CHUNK;
    const int i = cstart + t;
    const int tilebase = (c > 0) ? (c - 1) * CHUNK : 0;
    const int nkeys    = (c > 0) ? 256 : 128;
    const int cb = (c > 0) ? 128 : 0;

    // ---- stabilizer + alpha factors ----
    float alf[NC];
    float kstab;
    {
        float cm[NC];
        kstab = -3.4e38f;
#pragma unroll
        for (int cc = 0; cc < NC; cc++) {
            cm[cc] = __ldg(&g_chunkmax[h * NC + cc]);
            kstab = fmaxf(kstab, cm[cc]);
        }
#pragma unroll
        for (int cc = 0; cc < NC; cc++) alf[cc] = __expf(cm[cc] - kstab);
    }
    const float alphaP = (c > 0) ? alf[c - 1] : 0.f;
    const float alphaC = alf[c];

    // ---- cooperative tile load ----
    for (int f = t; f < nkeys * 16; f += 128) {
        int r = f >> 4, dv = f & 15;
        ((float4*)K_s)[r * 16 + dv] =
            ((const float4*)(qkv + ((size_t)((tilebase + r) * 3 + 1) * Hc + h) * Dc))[dv];
    }
    {
        const float4* kpsrc = (const float4*)(g_kprime + ((size_t)h * Lc + tilebase) * Mc);
        for (int f = t; f < nkeys * 6; f += 128) ((float4*)kp_s)[f] = kpsrc[f];
        for (int f = t; f < 384; f += 128) ((float4*)proj_s)[f] = ((const float4*)proj)[f];
    }
    // ---- prefix reconstruction: kvb (alpha-weighted), kb, sv ----
#pragma unroll
    for (int g = 0; g < 3; g++) {
        int f = t + 128 * g;
        float4 a = make_float4(0.f, 0.f, 0.f, 0.f);
        for (int cc = 0; cc < c; cc++) {
            float al = alf[cc];
            float4 x = __ldg((const float4*)g_pvsum + (size_t)(h * NC + cc) * 384 + f);
            a.x = fmaf(al, x.x, a.x); a.y = fmaf(al, x.y, a.y);
            a.z = fmaf(al, x.z, a.z); a.w = fmaf(al, x.w, a.w);
        }
        ((float4*)kvb_s)[f] = a;
    }
    if (t < Mc) {
        float a = (float)c * (CHUNK * EPSc);
        for (int cc = 0; cc < c; cc++)
            a = fmaf(alf[cc], __ldg(&g_psum[(h * NC + cc) * Mc + t]), a);
        kb_s[t] = a;
    }
    if (t < 16) {
        float4 a = make_float4(0.f, 0.f, 0.f, 0.f);
        for (int cc = 0; cc < c; cc++) {
            float4 x = __ldg((const float4*)(g_vsum + (size_t)(h * NC + cc) * Dc) + t);
            a.x += x.x; a.y += x.y; a.z += x.z; a.w += x.w;
        }
        ((float4*)sv_s)[t] = a;
    }
    __syncthreads();

    // ---- query state: q row + q' features (inline, proj from smem) ----
    U64 q2[32];
    {
        const ulonglong2* qr = (const ulonglong2*)(qkv + ((size_t)(i * 3) * Hc + h) * Dc);
#pragma unroll
        for (int u = 0; u < 16; u++) { ulonglong2 x = qr[u]; q2[2*u] = x.x; q2[2*u+1] = x.y; }
    }
    float xn;
    {
        U64 a0 = mul2(q2[0], q2[0]), a1 = mul2(q2[1], q2[1]);
        U64 a2 = mul2(q2[2], q2[2]), a3 = mul2(q2[3], q2[3]);
#pragma unroll
        for (int u = 4; u < 32; u += 4) {
            a0 = fma2(q2[u],   q2[u],   a0);
            a1 = fma2(q2[u+1], q2[u+1], a1);
            a2 = fma2(q2[u+2], q2[u+2], a2);
            a3 = fma2(q2[u+3], q2[u+3], a3);
        }
        xn = hadd2(add2(add2(a0, a1), add2(a2, a3))) * 0.0625f;
    }
    float xd[Mc];
    float qstab = -3.4e38f;
#pragma unroll
    for (int m = 0; m < Mc; m++) {
        float p = sdot64(proj_s + m * Dc, q2);
        xd[m] = p * DN;
        qstab = fmaxf(qstab, xd[m]);
    }
    U64 qp2[12];
    float qpsum = 0.f;
#pragma unroll
    for (int e = 0; e < 12; e++) {
        float a = __expf(xd[2*e]   - qstab) + EPSc;
        float b = __expf(xd[2*e+1] - qstab) + EPSc;
        qp2[e] = pack2(a, b);
        qpsum += a + b;
    }
    const float epsqp = EPSc * qpsum;

    const float gs = qstab - xn + kstab - LN24;
    float kbdot = 0.f;
#pragma unroll
    for (int e = 0; e < 12; e++) {
        float a, b; unpack2(a, b, qp2[e]);
        kbdot = fmaf(a, kb_s[2*e],     kbdot);
        kbdot = fmaf(b, kb_s[2*e + 1], kbdot);
    }

    // ---- pass 1: Z, Asc; cache (exp(s), g_eff) per key ----
    float2 sg[160];
    int idx = 0;
    float Z = 0.f, AscP = 0.f, AscC = 0.f;
    const int j0 = 32 * warp;
    if (c > 0) {
#pragma unroll 2
        for (int jr = j0; jr < 128; jr++) {
            float sd = sdot64(K_s + jr * Dc, q2);
            float gp = gdot24(kp_s + jr * Mc, qp2);
            float geff = fmaf(alphaP, gp, epsqp);
            float es = (jr >= t) ? exp2f(sd * SCL2E) : 0.f;
            float gg = (jr >= t) ? geff : 0.f;
            Z += es; AscP += gg;
            sg[idx++] = make_float2(es, gg);
        }
    }
    {
        const int jend = j0 + 32;
#pragma unroll 2
        for (int jc = 0; jc < jend; jc++) {
            float sd = sdot64(K_s + (cb + jc) * Dc, q2);
            float gp = gdot24(kp_s + (cb + jc) * Mc, qp2);
            float geff = fmaf(alphaC, gp, epsqp);
            float es = (jc <= t) ? exp2f(sd * SCL2E) : 0.f;
            float gg = (jc <= t) ? geff : 0.f;
            Z += es; AscC += gg;
            sg[idx++] = make_float2(es, gg);
        }
    }

    // ---- normalization scalars ----
    const float Asc = 0.875f * AscC - 0.125f * AscP;
    const float lse = __logf(Z);
    const float gln = __logf(fmaxf(kbdot + Asc, 1e-24f)) + gs;
    float a_ = fmaxf(lse, gln), b_ = fminf(lse, gln);
    const float lnorm = a_ + log1pf(__expf(b_ - a_));
    const float gps  = __expf(gs - lnorm);
    const float invZ = 1.f / Z;
    const float gpsP = -0.125f * gps;
    const float gpsC =  0.875f * gps;

    // ---- pass 2: output accumulation with cp.async V ring + cached coefs ----
    U64 o2[32];
#pragma unroll
    for (int u = 0; u < 32; u++) o2[u] = 0ULL;

    const unsigned ringw_u32 =
        (unsigned)__cvta_generic_to_shared(ring + warp * 512);
    const float* ringw = ring + warp * 512;
    int idx2 = 0;

    if (c > 0) {
        const int nbat = (128 - j0) >> 1;
#pragma unroll
        for (int p = 0; p < 3; p++) {
            int ra = j0 + 2*p;     if (ra > 127) ra = 127;
            int rb = j0 + 2*p + 1; if (rb > 127) rb = 127;
            stage2v(qkv, h, ringw_u32, p & 3, tilebase + ra, tilebase + rb, lane);
            CP_COMMIT();
        }
#pragma unroll 2
        for (int b = 0; b < nbat; b++) {
            int sp = b + 3;
            int ra = j0 + 2*sp;     if (ra > 127) ra = 127;
            int rb = j0 + 2*sp + 1; if (rb > 127) rb = 127;
            stage2v(qkv, h, ringw_u32, sp & 3, tilebase + ra, tilebase + rb, lane);
            CP_COMMIT();
            CP_WAIT(3);
            __syncwarp();
            const float* vb = ringw + (b & 3) * 128;
#pragma unroll
            for (int e = 0; e < 2; e++) {
                float2 sgv = sg[idx2++];
                float coef = fmaf(invZ, sgv.x, gpsP * sgv.y);
                vacc64(pack2(coef, coef), vb + e * 64, o2);
            }
        }
        CP_WAIT(0);
        __syncwarp();
    }
    {
        const int jend = j0 + 32;
        const int nbat = jend >> 1;
#pragma unroll
        for (int p = 0; p < 3; p++) {
            int ra = 2*p;     if (ra > jend - 1) ra = jend - 1;
            int rb = 2*p + 1; if (rb > jend - 1) rb = jend - 1;
            stage2v(qkv, h, ringw_u32, p & 3, cstart + ra, cstart + rb, lane);
            CP_COMMIT();
        }
#pragma unroll 2
        for (int b = 0; b < nbat; b++) {
            int sp = b + 3;
            int ra = 2*sp;     if (ra > jend - 1) ra = jend - 1;
            int rb = 2*sp + 1; if (rb > jend - 1) rb = jend - 1;
            stage2v(qkv, h, ringw_u32, sp & 3, cstart + ra, cstart + rb, lane);
            CP_COMMIT();
            CP_WAIT(3);
            __syncwarp();
            const float* vb = ringw + (b & 3) * 128;
#pragma unroll
            for (int e = 0; e < 2; e++) {
                float2 sgv = sg[idx2++];
                float coef = fmaf(invZ, sgv.x, gpsC * sgv.y);
                vacc64(pack2(coef, coef), vb + e * 64, o2);
            }
        }
        CP_WAIT(0);
        __syncwarp();
    }

    // ---- epilogue: o += gps * (q' . KVbase_alpha) + gps*qpsum*EPS * sv ----
#pragma unroll
    for (int e = 0; e < 12; e++) {
        float qa, qb; unpack2(qa, qb, qp2[e]);
        U64 ca  = pack2(gps * qa, gps * qa);
        U64 cb2 = pack2(gps * qb, gps * qb);
        const ulonglong2* r0 = (const ulonglong2*)(kvb_s + (2*e) * Dc);
        const ulonglong2* r1 = (const ulonglong2*)(kvb_s + (2*e + 1) * Dc);
#pragma unroll
        for (int u = 0; u < 16; u++) {
            ulonglong2 x0 = r0[u];
            ulonglong2 x1 = r1[u];
            o2[2*u]   = fma2(ca,  x0.x, o2[2*u]);
            o2[2*u+1] = fma2(ca,  x0.y, o2[2*u+1]);
            o2[2*u]   = fma2(cb2, x1.x, o2[2*u]);
            o2[2*u+1] = fma2(cb2, x1.y, o2[2*u+1]);
        }
    }
    {
        float csv = gps * epsqp;
        U64 c2 = pack2(csv, csv);
        vacc64(c2, sv_s, o2);
    }

    ulonglong2* orow = (ulonglong2*)(out + ((size_t)i * Hc + h) * Dc);
#pragma unroll
    for (int u = 0; u < 16; u++) {
        ulonglong2 w2; w2.x = o2[2*u]; w2.y = o2[2*u+1];
        orow[u] = w2;
    }
}

// ---------------- launch ----------------
extern "C" void kernel_launch(void* const* d_in, const int* in_sizes, int n_in,
                              void* d_out, int out_size)
{
    (void)out_size;
    const float* qkv  = (const float*)d_in[0];
    const float* proj = (const float*)d_in[1];
    if (n_in >= 2 && in_sizes[0] < in_sizes[1]) {
        const float* tmp = qkv; qkv = proj; proj = tmp;
    }
    float* out = (float*)d_out;

    cudaFuncSetAttribute(k12_prep, cudaFuncAttributeMaxDynamicSharedMemorySize,
                         SM12_FLOATS * (int)sizeof(float));
    cudaFuncSetAttribute(k4_main, cudaFuncAttributeMaxDynamicSharedMemorySize,
                         SM4_FLOATS * (int)sizeof(float));

    dim3 grid(NC, Hc);
    k12_prep<<<grid, 128, SM12_FLOATS * (int)sizeof(float)>>>(qkv, proj);
    k4_main <<<grid, 128, SM4_FLOATS * (int)sizeof(float)>>>(qkv, proj, out);
}